// round 6
// baseline (speedup 1.0000x reference)
#include <cuda_runtime.h>

// BinaryTree collocation probability — issue-minimized, 4 warps.
//   x = W[v_j + 2^20 - 1];  path[l] = ((u_k + 2^20) >> (20 - l)) - 1
//   out = prod_{l=0..20} sigmoid( dot(W[path[l]], x) )
//
// Round-3 finding: 21-warp version was LSU-issue bound (189 LDG warp-instrs
// x 1.82 cyc) + warp-ramp bound, not latency bound. This version uses 4 warps;
// warp w owns levels [6w, 6w+6) ∩ [0,21). Each lane: one float4 of x (loaded
// once) + one float4 per level -> 25 total LDG instructions. Six levels
// interleaved through one 5-step shfl-reduce tree; sigmoids spread over
// lanes 0..5; 3-step shfl product; one smem float/warp; 3-FMUL epilogue.

#define DEPTH   20
#define NLEVELS (DEPTH + 1)      // 21
#define NWARPS  4
#define LPW     6                // levels per warp (last warp has 3 valid)
#define NTHREADS (NWARPS * 32)   // 128

__global__ void __launch_bounds__(NTHREADS, 1)
binary_tree_kernel(const float* __restrict__ W,
                   const int* __restrict__ v_j_idx,
                   const int* __restrict__ u_k_idx,
                   float* __restrict__ out)
{
    __shared__ float s_p[NWARPS];

    const int tid  = threadIdx.x;
    const int wid  = tid >> 5;
    const int lane = tid & 31;

    // Dependent hop 1: scalar indices (broadcast loads, one line each).
    const int v_j = __ldg(v_j_idx);
    const int u_k = __ldg(u_k_idx);

    // 32-bit byte offsets: row * 512B, max 2^30.
    const char* base = (const char*)W;
    const unsigned leaf_off_b = ((unsigned)v_j + ((1u << DEPTH) - 1u)) << 9;
    const int      t          = u_k + (1 << DEPTH);

    // Dependent hop 2: x row (one float4 per lane, loaded ONCE).
    const float4 xb = __ldg((const float4*)(base + leaf_off_b) + lane);

    // Node rows for this warp's levels. Invalid tail levels (warp 3, i>=3)
    // contribute s=0 and are masked out of the sigmoid path anyway.
    float s[LPW];
    #pragma unroll
    for (int i = 0; i < LPW; ++i) {
        int level = wid * LPW + i;
        s[i] = 0.0f;
        if (level < NLEVELS) {
            unsigned node_off_b = (unsigned)((t >> (DEPTH - level)) - 1) << 9;
            float4 a = __ldg((const float4*)(base + node_off_b) + lane);
            s[i] = a.x * xb.x + a.y * xb.y + a.z * xb.z + a.w * xb.w;
        }
    }

    // 5-step shfl reduce, 6 independent levels interleaved (pipelined).
    #pragma unroll
    for (int off = 16; off > 0; off >>= 1) {
        #pragma unroll
        for (int i = 0; i < LPW; ++i)
            s[i] += __shfl_xor_sync(0xFFFFFFFFu, s[i], off);
    }

    // Lanes 0..5 each compute one sigmoid (parallel MUFU); others contribute 1.
    float sig = 1.0f;
    if (lane < LPW) {
        int level = wid * LPW + lane;
        if (level < NLEVELS)
            sig = __fdividef(1.0f, 1.0f + __expf(-s[lane]));
    }

    // Product over lanes 0..7 (lanes 6,7 hold 1.0) -> lane 0.
    sig *= __shfl_xor_sync(0xFFFFFFFFu, sig, 4);
    sig *= __shfl_xor_sync(0xFFFFFFFFu, sig, 2);
    sig *= __shfl_xor_sync(0xFFFFFFFFu, sig, 1);

    if (lane == 0) s_p[wid] = sig;
    __syncthreads();

    if (tid == 0)
        out[0] = (s_p[0] * s_p[1]) * (s_p[2] * s_p[3]);
}

extern "C" void kernel_launch(void* const* d_in, const int* in_sizes, int n_in,
                              void* d_out, int out_size)
{
    const float* W   = (const float*)d_in[0];
    const int*   vj  = (const int*)d_in[1];
    const int*   uk  = (const int*)d_in[2];
    float*       out = (float*)d_out;

    binary_tree_kernel<<<1, NTHREADS>>>(W, vj, uk, out);
}

// round 7
// speedup vs baseline: 1.4931x; 1.4931x over previous
#include <cuda_runtime.h>

// BinaryTree collocation probability — tail-chain-minimized, 4 warps.
//   x = W[v_j + 2^20 - 1];  path[l] = ((u_k + 2^20) >> (20 - l)) - 1
//   out = prod_{l=0..20} sigmoid( dot(W[path[l]], x) )
//
// Round-6 finding: kernel sits at a ~4.5us latency floor invariant to
// instruction count; only the post-load dependency chain is controllable.
// This version: 8 groups (4 warps x 2 half-warps) x 3 levels; 16 lanes per
// level with 2 float4/lane -> 4-step shfl reduce (was 5), product via
// 2 shfl-mults + 1 cross-half shfl (was 3 + smem path unchanged).

#define DEPTH   20
#define NLEVELS (DEPTH + 1)      // 21
#define NWARPS  4
#define LPG     3                // levels per 16-lane group; 8 groups * 3 = 24 slots
#define NTHREADS (NWARPS * 32)   // 128

__global__ void __launch_bounds__(NTHREADS, 1)
binary_tree_kernel(const float* __restrict__ W,
                   const int* __restrict__ v_j_idx,
                   const int* __restrict__ u_k_idx,
                   float* __restrict__ out)
{
    __shared__ float s_p[NWARPS];

    const int tid   = threadIdx.x;
    const int wid   = tid >> 5;
    const int glane = tid & 15;            // lane within 16-lane group
    const int group = tid >> 4;            // 0..7

    // Hop 1: scalar indices (broadcast loads).
    const int v_j = __ldg(v_j_idx);
    const int u_k = __ldg(u_k_idx);

    const char* base = (const char*)W;
    const unsigned leaf_off_b = ((unsigned)v_j + ((1u << DEPTH) - 1u)) << 9;
    const int      t          = u_k + (1 << DEPTH);

    // Hop 2: x row — 2 float4 per lane (32 float4 = 128 dims per 16 lanes).
    const float4* xv = (const float4*)(base + leaf_off_b);
    const float4  x0 = __ldg(xv + glane);
    const float4  x1 = __ldg(xv + glane + 16);

    // 3 levels per group; invalid slots (group 7) contribute sig = 1.
    float s[LPG];
    #pragma unroll
    for (int i = 0; i < LPG; ++i) {
        const int level = group * LPG + i;
        s[i] = 0.0f;
        if (level < NLEVELS) {
            const unsigned node_off_b = (unsigned)((t >> (DEPTH - level)) - 1) << 9;
            const float4* nv = (const float4*)(base + node_off_b);
            const float4  a0 = __ldg(nv + glane);
            const float4  a1 = __ldg(nv + glane + 16);
            // two parallel dot4 chains, one combining add
            float d0 = a0.x * x0.x + a0.y * x0.y + a0.z * x0.z + a0.w * x0.w;
            float d1 = a1.x * x1.x + a1.y * x1.y + a1.z * x1.z + a1.w * x1.w;
            s[i] = d0 + d1;
        }
    }

    // 4-step shfl reduce within each 16-lane half (offsets < 16 stay in-half).
    #pragma unroll
    for (int off = 8; off > 0; off >>= 1) {
        #pragma unroll
        for (int i = 0; i < LPG; ++i)
            s[i] += __shfl_xor_sync(0xFFFFFFFFu, s[i], off);
    }

    // Lanes 0..2 of each group: one sigmoid each (parallel MUFU). Others: 1.
    float sig = 1.0f;
    if (glane < LPG) {
        const int level = group * LPG + glane;
        if (level < NLEVELS) {
            // static selection (no dynamic register indexing)
            const float sv = (glane == 0) ? s[0] : ((glane == 1) ? s[1] : s[2]);
            sig = __fdividef(1.0f, 1.0f + __expf(-sv));
        }
    }

    // Product over lanes 0..3 of each group (lane 3 holds 1), then across halves.
    sig *= __shfl_xor_sync(0xFFFFFFFFu, sig, 1);
    sig *= __shfl_xor_sync(0xFFFFFFFFu, sig, 2);
    sig *= __shfl_xor_sync(0xFFFFFFFFu, sig, 16);   // combine the two 16-lane halves

    if ((tid & 31) == 0) s_p[wid] = sig;
    __syncthreads();

    if (tid == 0)
        out[0] = (s_p[0] * s_p[1]) * (s_p[2] * s_p[3]);
}

extern "C" void kernel_launch(void* const* d_in, const int* in_sizes, int n_in,
                              void* d_out, int out_size)
{
    const float* W   = (const float*)d_in[0];
    const int*   vj  = (const int*)d_in[1];
    const int*   uk  = (const int*)d_in[2];
    float*       out = (float*)d_out;

    binary_tree_kernel<<<1, NTHREADS>>>(W, vj, uk, out);
}